// round 3
// baseline (speedup 1.0000x reference)
#include <cuda_runtime.h>
#include <math_constants.h>

#define BB 16
#define CC 256
#define RR 64
#define HW 16384
#define HW4 (HW / 4)
#define NPLANE (BB * CC)
#define BATCH_F4 (CC * HW4)          // float4 elems per batch per array = 1048576
#define NEG_SLOPE 0.01f
#define GRID 592                     // 4 * 148; <= 4 * 152 too -> all co-resident
#define NTHR 256

// Scratch (__device__ globals: allocation-free rule)
__device__ float g_avg_r[NPLANE], g_avg_i[NPLANE];
__device__ float g_max_r[NPLANE], g_max_i[NPLANE];
__device__ float g_gr[NPLANE], g_gi[NPLANE];
__device__ int   g_cnt[BB];
__device__ int   g_ready[BB];

__global__ void reset_kernel() {
    if (threadIdx.x < BB) {
        g_cnt[threadIdx.x] = 0;
        g_ready[threadIdx.x] = 0;
    }
}

struct SMem {
    float red_sr[8], red_si[8], red_mr[8], red_mi[8];
    float in[4][CC];   // avg_r, avg_i, max_r, max_i for gate MLP
    float h[4][RR];    // hidden activations
    float gr[CC], gi[CC];
    int finisher;
};

__global__ __launch_bounds__(NTHR, 4) void fused_kernel(
    const float* __restrict__ xr, const float* __restrict__ xi,
    float* __restrict__ out,
    const float* __restrict__ w1r, const float* __restrict__ w1i,
    const float* __restrict__ b1r, const float* __restrict__ b1i,
    const float* __restrict__ w2r, const float* __restrict__ w2i,
    const float* __restrict__ b2r, const float* __restrict__ b2i)
{
    __shared__ SMem sm;
    const int bid = blockIdx.x;
    const int tid = threadIdx.x;
    const int wid = tid >> 5;
    const int lid = tid & 31;

    // Pipeline: step s pools batch s (blocks 0..255, one plane each),
    // then applies batch s-1 (all blocks). Gate(b) is computed inline by the
    // block that finishes batch b's 256th plane.
    for (int step = 0; step <= BB; step++) {
        // ---------------- pool batch `step` ----------------
        if (step < BB && bid < CC) {
            const int plane = step * CC + bid;
            const float4* pr = reinterpret_cast<const float4*>(xr) + (size_t)plane * HW4;
            const float4* pi = reinterpret_cast<const float4*>(xi) + (size_t)plane * HW4;

            float sr = 0.f, si = 0.f;
            float mr = -CUDART_INF_F, mi = -CUDART_INF_F;
#pragma unroll 4
            for (int i = tid; i < HW4; i += NTHR) {
                float4 a = pr[i];
                float4 b = pi[i];
                sr += (a.x + a.y) + (a.z + a.w);
                si += (b.x + b.y) + (b.z + b.w);
                mr = fmaxf(mr, fmaxf(fmaxf(a.x, a.y), fmaxf(a.z, a.w)));
                mi = fmaxf(mi, fmaxf(fmaxf(b.x, b.y), fmaxf(b.z, b.w)));
            }
#pragma unroll
            for (int o = 16; o > 0; o >>= 1) {
                sr += __shfl_down_sync(0xFFFFFFFFu, sr, o);
                si += __shfl_down_sync(0xFFFFFFFFu, si, o);
                mr = fmaxf(mr, __shfl_down_sync(0xFFFFFFFFu, mr, o));
                mi = fmaxf(mi, __shfl_down_sync(0xFFFFFFFFu, mi, o));
            }
            if (lid == 0) {
                sm.red_sr[wid] = sr; sm.red_si[wid] = si;
                sm.red_mr[wid] = mr; sm.red_mi[wid] = mi;
            }
            __syncthreads();
            if (tid == 0) {
                float tsr = sm.red_sr[0], tsi = sm.red_si[0];
                float tmr = sm.red_mr[0], tmi = sm.red_mi[0];
#pragma unroll
                for (int w = 1; w < 8; w++) {
                    tsr += sm.red_sr[w]; tsi += sm.red_si[w];
                    tmr = fmaxf(tmr, sm.red_mr[w]); tmi = fmaxf(tmi, sm.red_mi[w]);
                }
                g_avg_r[plane] = tsr * (1.0f / HW);
                g_avg_i[plane] = tsi * (1.0f / HW);
                g_max_r[plane] = tmr;
                g_max_i[plane] = tmi;
                __threadfence();
                int old = atomicAdd(&g_cnt[step], 1);
                sm.finisher = (old == CC - 1);
            }
            __syncthreads();

            // ---------------- gate MLP (finisher block only) ----------------
            if (sm.finisher) {
                const int gb = step * CC;
                sm.in[0][tid] = __ldcg(&g_avg_r[gb + tid]);
                sm.in[1][tid] = __ldcg(&g_avg_i[gb + tid]);
                sm.in[2][tid] = __ldcg(&g_max_r[gb + tid]);
                sm.in[3][tid] = __ldcg(&g_max_i[gb + tid]);
                __syncthreads();

                if (tid < 2 * RR) {   // {avg,max} x 64 hidden units
                    const int which = tid >> 6;
                    const int r = tid & (RR - 1);
                    const float* zr = sm.in[2 * which];
                    const float* zi = sm.in[2 * which + 1];
                    float yr = b1r[r], yi = b1i[r];
#pragma unroll 8
                    for (int c = 0; c < CC; c++) {
                        const float wr = w1r[r * CC + c];
                        const float wi = w1i[r * CC + c];
                        const float zrc = zr[c], zic = zi[c];
                        yr = fmaf(zrc, wr, fmaf(-zic, wi, yr));
                        yi = fmaf(zrc, wi, fmaf(zic, wr, yi));
                    }
                    yr = (yr > 0.f) ? yr : NEG_SLOPE * yr;
                    yi = (yi > 0.f) ? yi : NEG_SLOPE * yi;
                    sm.h[2 * which][r] = yr;
                    sm.h[2 * which + 1][r] = yi;
                }
                __syncthreads();

                {   // layer 2 both branches + sigmoid, thread = channel
                    float ar = b2r[tid], ai = b2i[tid];
                    float mr2 = ar, mi2 = ai;
#pragma unroll 8
                    for (int j = 0; j < RR; j++) {
                        const float wr = w2r[tid * RR + j];
                        const float wi = w2i[tid * RR + j];
                        const float har = sm.h[0][j], hai = sm.h[1][j];
                        const float hmr = sm.h[2][j], hmi = sm.h[3][j];
                        ar = fmaf(har, wr, fmaf(-hai, wi, ar));
                        ai = fmaf(har, wi, fmaf(hai, wr, ai));
                        mr2 = fmaf(hmr, wr, fmaf(-hmi, wi, mr2));
                        mi2 = fmaf(hmr, wi, fmaf(hmi, wr, mi2));
                    }
                    const float zr = ar + mr2;
                    const float zi = ai + mi2;
                    g_gr[gb + tid] = 1.0f / (1.0f + expf(-zr));
                    g_gi[gb + tid] = 1.0f / (1.0f + expf(-zi));
                }
                __threadfence();   // every writing thread orders its g_g* stores
                __syncthreads();
                if (tid == 0) atomicExch(&g_ready[step], 1);
            }
        }

        // ---------------- apply batch `step-1` ----------------
        const int ab = step - 1;
        if (ab >= 0) {
            if (tid == 0) {
                while (atomicAdd(&g_ready[ab], 0) == 0) __nanosleep(128);
            }
            __syncthreads();
            sm.gr[tid] = __ldcg(&g_gr[ab * CC + tid]);
            sm.gi[tid] = __ldcg(&g_gi[ab * CC + tid]);
            __syncthreads();

            const size_t base = (size_t)ab * BATCH_F4;
            const float4* pr = reinterpret_cast<const float4*>(xr) + base;
            const float4* pi = reinterpret_cast<const float4*>(xi) + base;
            float4* por = reinterpret_cast<float4*>(out) + base;
            float4* poi = reinterpret_cast<float4*>(out) + (size_t)NPLANE * HW4 + base;

            for (int i = bid * NTHR + tid; i < BATCH_F4; i += GRID * NTHR) {
                const int c = i >> 12;          // i / (HW/4)
                const float gr = sm.gr[c];
                const float gi = sm.gi[c];
                const float4 a = __ldcs(pr + i);
                const float4 b = __ldcs(pi + i);
                float4 r, m;
                r.x = fmaf(a.x, gr, -b.x * gi);
                r.y = fmaf(a.y, gr, -b.y * gi);
                r.z = fmaf(a.z, gr, -b.z * gi);
                r.w = fmaf(a.w, gr, -b.w * gi);
                m.x = fmaf(a.x, gi, b.x * gr);
                m.y = fmaf(a.y, gi, b.y * gr);
                m.z = fmaf(a.z, gi, b.z * gr);
                m.w = fmaf(a.w, gi, b.w * gr);
                __stcs(por + i, r);
                __stcs(poi + i, m);
            }
            __syncthreads();
        }
    }
}

extern "C" void kernel_launch(void* const* d_in, const int* in_sizes, int n_in,
                              void* d_out, int out_size) {
    const float* xr  = (const float*)d_in[0];
    const float* xi  = (const float*)d_in[1];
    const float* w1r = (const float*)d_in[2];
    const float* w1i = (const float*)d_in[3];
    const float* b1r = (const float*)d_in[4];
    const float* b1i = (const float*)d_in[5];
    const float* w2r = (const float*)d_in[6];
    const float* w2i = (const float*)d_in[7];
    const float* b2r = (const float*)d_in[8];
    const float* b2i = (const float*)d_in[9];
    float* out = (float*)d_out;

    reset_kernel<<<1, 32>>>();
    fused_kernel<<<GRID, NTHR>>>(xr, xi, out,
                                 w1r, w1i, b1r, b1i,
                                 w2r, w2i, b2r, b2i);
}

// round 4
// speedup vs baseline: 1.7545x; 1.7545x over previous
#include <cuda_runtime.h>
#include <math_constants.h>

#define BB 16
#define CC 256
#define RR 64
#define HW 16384
#define HW4 (HW / 4)                 // 4096 float4 per plane per comp
#define HALF4 (HW4 / 2)              // 2048 float4 per half-plane
#define NPLANE (BB * CC)
#define BATCH_F4 (CC * HW4)          // 1048576 float4 per batch per comp
#define NEG_SLOPE 0.01f
#define GRID 592                     // 4 * 148, all co-resident
#define POOLB 512                    // pooling blocks: one half-plane each
#define SPARE (GRID - POOLB)         // 80 spare blocks; one per step runs the gate
#define NTHR 256
#define APPLY_STRIDE (GRID * NTHR)   // 151552

// ---- scratch (__device__ globals; allocation-free rule) ----
__device__ float g_hsr[BB][POOLB], g_hsi[BB][POOLB];   // half-plane sums
__device__ float g_hmr[BB][POOLB], g_hmi[BB][POOLB];   // half-plane maxes
__device__ float g_gr[NPLANE], g_gi[NPLANE];           // gates
__device__ int   g_cnt[BB];
__device__ int   g_ready[BB];

__global__ void reset_kernel() {
    if (threadIdx.x < BB) {
        g_cnt[threadIdx.x] = 0;
        g_ready[threadIdx.x] = 0;
    }
}

struct SMem {
    float red_sr[8], red_si[8], red_mr[8], red_mi[8];
    float in[4][CC];   // avg_r, avg_i, max_r, max_i (gate block)
    float h[4][RR];    // hidden activations (gate block)
    float gr[CC], gi[CC];  // gate table for apply
};

__global__ __launch_bounds__(NTHR, 4) void fused_kernel(
    const float* __restrict__ xr, const float* __restrict__ xi,
    float* __restrict__ out,
    const float* __restrict__ w1r, const float* __restrict__ w1i,
    const float* __restrict__ b1r, const float* __restrict__ b1i,
    const float* __restrict__ w2r, const float* __restrict__ w2i,
    const float* __restrict__ b2r, const float* __restrict__ b2i)
{
    __shared__ SMem sm;
    const int bid = blockIdx.x;
    const int tid = threadIdx.x;
    const int wid = tid >> 5;
    const int lid = tid & 31;

    for (int s = 0; s <= BB; s++) {
        // ----------------- pool: batch s, one half-plane per block -----------------
        if (s < BB && bid < POOLB) {
            const int plane = s * CC + (bid >> 1);
            const size_t base = (size_t)plane * HW4 + (size_t)(bid & 1) * HALF4;
            const float4* pr = reinterpret_cast<const float4*>(xr) + base;
            const float4* pi = reinterpret_cast<const float4*>(xi) + base;

            float sr = 0.f, si = 0.f;
            float mr = -CUDART_INF_F, mi = -CUDART_INF_F;
#pragma unroll
            for (int k = 0; k < HALF4 / NTHR; k++) {       // 8 iters
                const int i = k * NTHR + tid;
                float4 a = __ldcg(pr + i);                 // allocate L2, skip L1
                float4 b = __ldcg(pi + i);
                sr += (a.x + a.y) + (a.z + a.w);
                si += (b.x + b.y) + (b.z + b.w);
                mr = fmaxf(mr, fmaxf(fmaxf(a.x, a.y), fmaxf(a.z, a.w)));
                mi = fmaxf(mi, fmaxf(fmaxf(b.x, b.y), fmaxf(b.z, b.w)));
            }
#pragma unroll
            for (int o = 16; o > 0; o >>= 1) {
                sr += __shfl_down_sync(0xFFFFFFFFu, sr, o);
                si += __shfl_down_sync(0xFFFFFFFFu, si, o);
                mr = fmaxf(mr, __shfl_down_sync(0xFFFFFFFFu, mr, o));
                mi = fmaxf(mi, __shfl_down_sync(0xFFFFFFFFu, mi, o));
            }
            if (lid == 0) {
                sm.red_sr[wid] = sr; sm.red_si[wid] = si;
                sm.red_mr[wid] = mr; sm.red_mi[wid] = mi;
            }
            __syncthreads();
            if (tid == 0) {
                float tsr = sm.red_sr[0], tsi = sm.red_si[0];
                float tmr = sm.red_mr[0], tmi = sm.red_mi[0];
#pragma unroll
                for (int w = 1; w < 8; w++) {
                    tsr += sm.red_sr[w]; tsi += sm.red_si[w];
                    tmr = fmaxf(tmr, sm.red_mr[w]); tmi = fmaxf(tmi, sm.red_mi[w]);
                }
                g_hsr[s][bid] = tsr; g_hsi[s][bid] = tsi;
                g_hmr[s][bid] = tmr; g_hmi[s][bid] = tmi;
                __threadfence();
                atomicAdd(&g_cnt[s], 1);
            }
            __syncthreads();
        }

        // ----------------- gate: rotating spare block computes MLP(s) -----------------
        if (s < BB && bid >= POOLB && (bid - POOLB) == (s % SPARE)) {
            if (tid == 0) {
                while (atomicAdd(&g_cnt[s], 0) < POOLB) __nanosleep(64);
            }
            __syncthreads();
            __threadfence();
            {   // combine half-plane partials -> pooled per-channel values
                const int h0 = 2 * tid, h1 = 2 * tid + 1;
                sm.in[0][tid] = (__ldcg(&g_hsr[s][h0]) + __ldcg(&g_hsr[s][h1])) * (1.0f / HW);
                sm.in[1][tid] = (__ldcg(&g_hsi[s][h0]) + __ldcg(&g_hsi[s][h1])) * (1.0f / HW);
                sm.in[2][tid] = fmaxf(__ldcg(&g_hmr[s][h0]), __ldcg(&g_hmr[s][h1]));
                sm.in[3][tid] = fmaxf(__ldcg(&g_hmi[s][h0]), __ldcg(&g_hmi[s][h1]));
            }
            __syncthreads();
            if (tid < 2 * RR) {   // layer 1: {avg,max} x 64 hidden units
                const int which = tid >> 6;
                const int r = tid & (RR - 1);
                const float* zr = sm.in[2 * which];
                const float* zi = sm.in[2 * which + 1];
                float yr = b1r[r], yi = b1i[r];
#pragma unroll 8
                for (int c = 0; c < CC; c++) {
                    const float wr = w1r[r * CC + c];
                    const float wi = w1i[r * CC + c];
                    const float zrc = zr[c], zic = zi[c];
                    yr = fmaf(zrc, wr, fmaf(-zic, wi, yr));
                    yi = fmaf(zrc, wi, fmaf(zic, wr, yi));
                }
                yr = (yr > 0.f) ? yr : NEG_SLOPE * yr;
                yi = (yi > 0.f) ? yi : NEG_SLOPE * yi;
                sm.h[2 * which][r] = yr;
                sm.h[2 * which + 1][r] = yi;
            }
            __syncthreads();
            {   // layer 2 both branches + sigmoid; thread = channel
                float ar = b2r[tid], ai = b2i[tid];
                float mr2 = ar, mi2 = ai;
#pragma unroll 8
                for (int j = 0; j < RR; j++) {
                    const float wr = w2r[tid * RR + j];
                    const float wi = w2i[tid * RR + j];
                    const float har = sm.h[0][j], hai = sm.h[1][j];
                    const float hmr = sm.h[2][j], hmi = sm.h[3][j];
                    ar = fmaf(har, wr, fmaf(-hai, wi, ar));
                    ai = fmaf(har, wi, fmaf(hai, wr, ai));
                    mr2 = fmaf(hmr, wr, fmaf(-hmi, wi, mr2));
                    mi2 = fmaf(hmr, wi, fmaf(hmi, wr, mi2));
                }
                const float zr = ar + mr2;
                const float zi = ai + mi2;
                g_gr[s * CC + tid] = 1.0f / (1.0f + expf(-zr));
                g_gi[s * CC + tid] = 1.0f / (1.0f + expf(-zi));
            }
            __threadfence();
            __syncthreads();
            if (tid == 0) atomicExch(&g_ready[s], 1);
        }

        // ----------------- apply: batch s-1 (grid-strided, all blocks) -----------------
        const int ab = s - 1;
        if (ab >= 0) {
            if (tid == 0) {
                while (atomicAdd(&g_ready[ab], 0) == 0) __nanosleep(64);
            }
            __syncthreads();
            sm.gr[tid] = __ldcg(&g_gr[ab * CC + tid]);
            sm.gi[tid] = __ldcg(&g_gi[ab * CC + tid]);
            __syncthreads();

            const size_t base = (size_t)ab * BATCH_F4;
            const float4* pr = reinterpret_cast<const float4*>(xr) + base;
            const float4* pi = reinterpret_cast<const float4*>(xi) + base;
            float4* por = reinterpret_cast<float4*>(out) + base;
            float4* poi = reinterpret_cast<float4*>(out) + (size_t)NPLANE * HW4 + base;

            for (int i = bid * NTHR + tid; i < BATCH_F4; i += APPLY_STRIDE) {
                const int c = i >> 12;            // i / HW4
                const float gr = sm.gr[c];
                const float gi = sm.gi[c];
                const float4 a = __ldcs(pr + i);  // L2 hit expected; evict-first after
                const float4 b = __ldcs(pi + i);
                float4 r, m;
                r.x = fmaf(a.x, gr, -b.x * gi);
                r.y = fmaf(a.y, gr, -b.y * gi);
                r.z = fmaf(a.z, gr, -b.z * gi);
                r.w = fmaf(a.w, gr, -b.w * gi);
                m.x = fmaf(a.x, gi, b.x * gr);
                m.y = fmaf(a.y, gi, b.y * gr);
                m.z = fmaf(a.z, gi, b.z * gr);
                m.w = fmaf(a.w, gi, b.w * gr);
                __stcs(por + i, r);               // streaming store: don't pollute L2
                __stcs(poi + i, m);
            }
            __syncthreads();   // smem gate table reused next step
        }
    }
}

extern "C" void kernel_launch(void* const* d_in, const int* in_sizes, int n_in,
                              void* d_out, int out_size) {
    const float* xr  = (const float*)d_in[0];
    const float* xi  = (const float*)d_in[1];
    const float* w1r = (const float*)d_in[2];
    const float* w1i = (const float*)d_in[3];
    const float* b1r = (const float*)d_in[4];
    const float* b1i = (const float*)d_in[5];
    const float* w2r = (const float*)d_in[6];
    const float* w2i = (const float*)d_in[7];
    const float* b2r = (const float*)d_in[8];
    const float* b2i = (const float*)d_in[9];
    float* out = (float*)d_out;

    reset_kernel<<<1, 32>>>();
    fused_kernel<<<GRID, NTHR>>>(xr, xi, out,
                                 w1r, w1i, b1r, b1i,
                                 w2r, w2i, b2r, b2i);
}